// round 4
// baseline (speedup 1.0000x reference)
#include <cuda_runtime.h>
#include <math.h>

#define Bb 64
#define Hh 512
#define Gg 2048
#define Vv 32000
#define Tt 24

// -------- scratch (static device globals; no allocation) --------
__device__ float g_h[Bb*Hh];
__device__ float g_c[Bb*Hh];
__device__ float g_gates[Bb*Gg];
__device__ float g_xv[Gg];
__device__ unsigned long long g_amax[Bb];
__device__ int   g_idx[Bb];
__device__ float g_mask[Bb];

__device__ __forceinline__ unsigned int fkey(float f){
    unsigned int u = __float_as_uint(f);
    return (u & 0x80000000u) ? ~u : (u | 0x80000000u);
}

// -------- init: copy state, set mask=1 --------
__global__ void k_init(const float* __restrict__ eh, const float* __restrict__ ec){
    int i = blockIdx.x*blockDim.x + threadIdx.x;
    if (i < Bb*Hh){ g_h[i] = eh[i]; g_c[i] = ec[i]; }
    if (i < Bb){ g_mask[i] = 1.0f; g_amax[i] = 0ull; g_idx[i] = 0; }
}

// -------- xv[j] = dot(W_ih[j,:], x0)  (step-0 input contribution) --------
__global__ void k_xv(const float* __restrict__ W_ih, const float* __restrict__ x0){
    int j = blockIdx.x;
    const float* row = W_ih + (size_t)j*Vv;
    float s = 0.f;
    for (int v = threadIdx.x; v < Vv; v += 256) s += row[v]*x0[v];
    __shared__ float red[256];
    red[threadIdx.x] = s; __syncthreads();
    for (int o = 128; o > 0; o >>= 1){
        if (threadIdx.x < o) red[threadIdx.x] += red[threadIdx.x+o];
        __syncthreads();
    }
    if (threadIdx.x == 0) g_xv[j] = red[0];
}

// -------- gates GEMM: gates[b,j] = bias[j] + dot(W_hh[j,:], h[b,:]) + xterm --------
// grid 128 blocks (16 j each), 256 threads; each thread: 1 j x 4 b
__global__ void __launch_bounds__(256) k_gates(
    const float* __restrict__ W_hh, const float* __restrict__ b_ih,
    const float* __restrict__ b_hh, const float* __restrict__ W_ih, int use_xv)
{
    __shared__ float sW[32*16];
    __shared__ float sH[32*68];
    int tx = threadIdx.x;
    int j0 = blockIdx.x * 16;
    int tj = tx >> 4, tb = tx & 15;
    float acc[4] = {0.f,0.f,0.f,0.f};
    int lj = tx >> 3, lkq = tx & 7;     // W loader (tx<128)

    for (int k0 = 0; k0 < Hh; k0 += 32){
        __syncthreads();
        if (tx < 128){
            float4 w = *(const float4*)(W_hh + (size_t)(j0+lj)*Hh + k0 + lkq*4);
            sW[(lkq*4+0)*16+lj] = w.x;
            sW[(lkq*4+1)*16+lj] = w.y;
            sW[(lkq*4+2)*16+lj] = w.z;
            sW[(lkq*4+3)*16+lj] = w.w;
        }
        #pragma unroll
        for (int s = 0; s < 2; s++){
            int e = tx*2 + s;
            int b = e >> 3, kq = e & 7;
            float4 hv = *(const float4*)(g_h + b*Hh + k0 + kq*4);
            sH[(kq*4+0)*68+b] = hv.x;
            sH[(kq*4+1)*68+b] = hv.y;
            sH[(kq*4+2)*68+b] = hv.z;
            sH[(kq*4+3)*68+b] = hv.w;
        }
        __syncthreads();
        #pragma unroll
        for (int k = 0; k < 32; k++){
            float w = sW[k*16 + tj];
            float4 hb = *(const float4*)(sH + k*68 + tb*4);
            acc[0] = fmaf(w, hb.x, acc[0]);
            acc[1] = fmaf(w, hb.y, acc[1]);
            acc[2] = fmaf(w, hb.z, acc[2]);
            acc[3] = fmaf(w, hb.w, acc[3]);
        }
    }
    int j = j0 + tj;
    float bias = b_ih[j] + b_hh[j];
    #pragma unroll
    for (int i = 0; i < 4; i++){
        int b = tb*4 + i;
        float x = use_xv ? g_xv[j] : W_ih[(size_t)j*Vv + g_idx[b]];
        g_gates[b*Gg + j] = acc[i] + bias + x;
    }
}

// -------- LSTM elementwise --------
__global__ void k_lstm(){
    int b = blockIdx.x, hh = threadIdx.x;
    const float* gr = g_gates + b*Gg;
    float gi = gr[hh], gf = gr[hh+512], gg = gr[hh+1024], go = gr[hh+1536];
    float c  = g_c[b*Hh + hh];
    float si = 1.f/(1.f+expf(-gi));
    float sf = 1.f/(1.f+expf(-gf));
    float so = 1.f/(1.f+expf(-go));
    float cn = sf*c + si*tanhf(gg);
    float hn = so*tanhf(cn);
    g_c[b*Hh+hh] = cn;
    g_h[b*Hh+hh] = hn;
    if (b == 0 && hh < Bb) g_amax[hh] = 0ull;  // reset before this step's logits
}

// -------- logits GEMM + argmax partials + output writes --------
// grid 250 blocks (128 v each), 256 threads; each thread: 4 b x 8 v
__global__ void __launch_bounds__(256) k_logits(
    const float* __restrict__ W_out, const float* __restrict__ b_out,
    float* __restrict__ out, int t)
{
    __shared__ float sW[16*128];
    __shared__ float sH[16*68];
    __shared__ unsigned long long skey[64];
    int tx = threadIdx.x;
    int vblk = blockIdx.x * 128;
    int vg = tx >> 4, bg = tx & 15;
    if (tx < 64) skey[tx] = 0ull;

    float acc[4][8];
    #pragma unroll
    for (int i = 0; i < 4; i++)
        #pragma unroll
        for (int j = 0; j < 8; j++) acc[i][j] = 0.f;

    int lv = tx >> 1, lkq = (tx & 1) * 2;   // W loader: 2 float4/thread
    int lb = tx >> 2, lbkq = tx & 3;        // H loader: 1 float4/thread

    for (int k0 = 0; k0 < Hh; k0 += 16){
        __syncthreads();
        {
            const float* wp = W_out + (size_t)(vblk+lv)*Hh + k0 + lkq*4;
            float4 w0 = *(const float4*)(wp);
            float4 w1 = *(const float4*)(wp + 4);
            sW[(lkq*4+0)*128+lv] = w0.x; sW[(lkq*4+1)*128+lv] = w0.y;
            sW[(lkq*4+2)*128+lv] = w0.z; sW[(lkq*4+3)*128+lv] = w0.w;
            sW[(lkq*4+4)*128+lv] = w1.x; sW[(lkq*4+5)*128+lv] = w1.y;
            sW[(lkq*4+6)*128+lv] = w1.z; sW[(lkq*4+7)*128+lv] = w1.w;
        }
        {
            float4 hv = *(const float4*)(g_h + lb*Hh + k0 + lbkq*4);
            sH[(lbkq*4+0)*68+lb] = hv.x; sH[(lbkq*4+1)*68+lb] = hv.y;
            sH[(lbkq*4+2)*68+lb] = hv.z; sH[(lbkq*4+3)*68+lb] = hv.w;
        }
        __syncthreads();
        #pragma unroll
        for (int k = 0; k < 16; k++){
            float4 hb = *(const float4*)(sH + k*68 + bg*4);
            float4 wa = *(const float4*)(sW + k*128 + vg*8);
            float4 wb = *(const float4*)(sW + k*128 + vg*8 + 4);
            float hv[4] = {hb.x, hb.y, hb.z, hb.w};
            float wv[8] = {wa.x, wa.y, wa.z, wa.w, wb.x, wb.y, wb.z, wb.w};
            #pragma unroll
            for (int i = 0; i < 4; i++)
                #pragma unroll
                for (int j = 0; j < 8; j++)
                    acc[i][j] = fmaf(hv[i], wv[j], acc[i][j]);
        }
    }

    // epilogue: bias, write logits + zero predicts, argmax partials
    size_t base = (size_t)t * Bb * Vv;
    float* logits = out + 49152000ull;   // T*B*V
    unsigned long long best[4] = {0ull,0ull,0ull,0ull};
    #pragma unroll
    for (int j = 0; j < 8; j++){
        int v = vblk + vg*8 + j;
        float bo = b_out[v];
        #pragma unroll
        for (int i = 0; i < 4; i++){
            int b = bg*4 + i;
            float val = acc[i][j] + bo;
            size_t o = base + (size_t)b*Vv + v;
            logits[o] = val;
            out[o] = 0.f;   // predicts zero-fill
            unsigned long long key =
                ((unsigned long long)fkey(val) << 32) |
                (unsigned long long)(0xFFFFFFFFu - (unsigned int)v);
            if (key > best[i]) best[i] = key;
        }
    }
    #pragma unroll
    for (int i = 0; i < 4; i++) atomicMax(&skey[bg*4 + i], best[i]);
    __syncthreads();
    if (tx < 64 && skey[tx]) atomicMax(&g_amax[tx], skey[tx]);
}

// -------- finalize: scatter one-hot, write mask, update state --------
__global__ void k_final(float* __restrict__ out, int t){
    int b = threadIdx.x;
    if (b >= Bb) return;
    unsigned long long key = g_amax[b];
    int idx = (int)(0xFFFFFFFFu - (unsigned int)(key & 0xFFFFFFFFull));
    out[(size_t)t*Bb*Vv + (size_t)b*Vv + idx] = 1.0f;       // predicts one-hot
    out[98304000ull + (size_t)t*Bb + b] = g_mask[b];        // masks (pre-update)
    if (idx == 0) g_mask[b] = 0.f;                          // EOS mask update
    g_idx[b] = idx;
}

extern "C" void kernel_launch(void* const* d_in, const int* in_sizes, int n_in,
                              void* d_out, int out_size){
    const float* eh    = (const float*)d_in[0];
    const float* ec    = (const float*)d_in[1];
    const float* W_ih  = (const float*)d_in[2];
    const float* W_hh  = (const float*)d_in[3];
    const float* b_ih  = (const float*)d_in[4];
    const float* b_hh  = (const float*)d_in[5];
    const float* W_out = (const float*)d_in[6];
    const float* b_out = (const float*)d_in[7];
    const float* x0    = (const float*)d_in[8];
    float* out = (float*)d_out;

    k_init<<<128, 256>>>(eh, ec);
    k_xv<<<Gg, 256>>>(W_ih, x0);
    for (int t = 0; t < Tt; t++){
        k_gates<<<128, 256>>>(W_hh, b_ih, b_hh, W_ih, t == 0 ? 1 : 0);
        k_lstm<<<Bb, Hh>>>();
        k_logits<<<250, 256>>>(W_out, b_out, out, t);
        k_final<<<1, 64>>>(out, t);
    }
}

// round 5
// speedup vs baseline: 1.0761x; 1.0761x over previous
#include <cuda_runtime.h>
#include <math.h>

#define Bb 64
#define Hh 512
#define Gg 2048
#define Vv 32000
#define Tt 24

// -------- scratch (static device globals; no allocation) --------
__device__ float g_hbuf[2][Bb*Hh];   // ping-pong hidden state
__device__ float g_c[Bb*Hh];
__device__ float g_xv[Gg];
__device__ unsigned long long g_amax[Tt*Bb];  // per-step argmax keys (no resets needed)
__device__ float g_mask[Bb];

__device__ __forceinline__ unsigned int fkey(float f){
    unsigned int u = __float_as_uint(f);
    return (u & 0x80000000u) ? ~u : (u | 0x80000000u);
}
__device__ __forceinline__ int dekey(unsigned long long key){
    return (int)(0xFFFFFFFFu - (unsigned int)(key & 0xFFFFFFFFull));
}

// -------- init: copy state, set mask=1, zero per-step amax --------
__global__ void k_init(const float* __restrict__ eh, const float* __restrict__ ec){
    int i = blockIdx.x*blockDim.x + threadIdx.x;
    if (i < Bb*Hh){ g_hbuf[0][i] = eh[i]; g_c[i] = ec[i]; }
    if (i < Bb) g_mask[i] = 1.0f;
    if (i < Tt*Bb) g_amax[i] = 0ull;
}

// -------- xv[j] = dot(W_ih[j,:], x0)  (step-0 input contribution) --------
__global__ void k_xv(const float* __restrict__ W_ih, const float* __restrict__ x0){
    int j = blockIdx.x;
    const float* row = W_ih + (size_t)j*Vv;
    float s = 0.f;
    for (int v = threadIdx.x; v < Vv; v += 256) s += row[v]*x0[v];
    __shared__ float red[256];
    red[threadIdx.x] = s; __syncthreads();
    for (int o = 128; o > 0; o >>= 1){
        if (threadIdx.x < o) red[threadIdx.x] += red[threadIdx.x+o];
        __syncthreads();
    }
    if (threadIdx.x == 0) g_xv[j] = red[0];
}

// -------- fused gates GEMM + LSTM (+ step t-1 finalize in block 0) --------
// grid 128 = 32 h-tiles x 4 b-tiles. Block owns 16 h (=> 64 W_hh rows over
// 4 gates) x 16 b. Reads g_hbuf[t&1], writes g_hbuf[(t+1)&1] (ping-pong).
__global__ void __launch_bounds__(256) k_gates(
    const float* __restrict__ W_hh, const float* __restrict__ b_ih,
    const float* __restrict__ b_hh, const float* __restrict__ W_ih,
    float* __restrict__ out, int t)
{
    __shared__ float sW[32*64];
    __shared__ float sH[32*20];
    __shared__ float sG[64*17];
    int tx = threadIdx.x;
    int ht = blockIdx.x >> 2, bt = blockIdx.x & 3;
    const float* hin  = g_hbuf[t & 1];
    float*       hout = g_hbuf[(t + 1) & 1];

    // finalize duties for step t-1 (one-hot scatter, mask write+update)
    if (t > 0 && blockIdx.x == 0 && tx < Bb){
        unsigned long long key = g_amax[(t-1)*Bb + tx];
        int idx = dekey(key);
        out[(size_t)(t-1)*Bb*Vv + (size_t)tx*Vv + idx] = 1.0f;  // predicts one-hot
        out[98304000ull + (size_t)(t-1)*Bb + tx] = g_mask[tx];  // masks (pre-update)
        if (idx == 0) g_mask[tx] = 0.f;
    }

    int r = tx >> 2, bq = tx & 3;          // r: 64 gate-rows, bq: 4 b's (x4)
    int gate = r >> 4, h_l = r & 15;
    int j = gate*512 + ht*16 + h_l;
    float bias = b_ih[j] + b_hh[j];
    float xterm[4];
    if (t == 0){
        float xv = g_xv[j];
        #pragma unroll
        for (int i = 0; i < 4; i++) xterm[i] = xv;
    } else {
        #pragma unroll
        for (int i = 0; i < 4; i++){
            int b = bt*16 + bq*4 + i;
            int idx = dekey(g_amax[(t-1)*Bb + b]);
            xterm[i] = W_ih[(size_t)j*Vv + idx];
        }
    }

    float acc[4] = {0.f,0.f,0.f,0.f};
    for (int k0 = 0; k0 < Hh; k0 += 32){
        __syncthreads();
        #pragma unroll
        for (int s = 0; s < 2; s++){           // W: 2 float4/thread
            int e = tx*2 + s;
            int row = e >> 3, kq = e & 7;
            int jr = (row >> 4)*512 + ht*16 + (row & 15);
            float4 w = *(const float4*)(W_hh + (size_t)jr*Hh + k0 + kq*4);
            sW[(kq*4+0)*64+row] = w.x;
            sW[(kq*4+1)*64+row] = w.y;
            sW[(kq*4+2)*64+row] = w.z;
            sW[(kq*4+3)*64+row] = w.w;
        }
        if (tx < 128){                          // H: 16b x 32k
            int lb = tx >> 3, kq = tx & 7;
            float4 hv = *(const float4*)(hin + (bt*16+lb)*Hh + k0 + kq*4);
            sH[(kq*4+0)*20+lb] = hv.x;
            sH[(kq*4+1)*20+lb] = hv.y;
            sH[(kq*4+2)*20+lb] = hv.z;
            sH[(kq*4+3)*20+lb] = hv.w;
        }
        __syncthreads();
        #pragma unroll
        for (int k = 0; k < 32; k++){
            float w = sW[k*64 + r];
            float4 h4 = *(const float4*)(sH + k*20 + bq*4);
            acc[0] = fmaf(w, h4.x, acc[0]);
            acc[1] = fmaf(w, h4.y, acc[1]);
            acc[2] = fmaf(w, h4.z, acc[2]);
            acc[3] = fmaf(w, h4.w, acc[3]);
        }
    }
    // stage gates to smem
    #pragma unroll
    for (int i = 0; i < 4; i++) sG[r*17 + bq*4 + i] = acc[i] + bias + xterm[i];
    __syncthreads();

    // LSTM elementwise: thread = (h2 = tx&15, b2 = tx>>4)
    int h2 = tx & 15, b2 = tx >> 4;
    float gi = sG[( 0 + h2)*17 + b2];
    float gf = sG[(16 + h2)*17 + b2];
    float gg = sG[(32 + h2)*17 + b2];
    float go = sG[(48 + h2)*17 + b2];
    int b = bt*16 + b2, h = ht*16 + h2;
    float c  = g_c[b*Hh + h];
    float si = 1.f/(1.f+expf(-gi));
    float sf = 1.f/(1.f+expf(-gf));
    float so = 1.f/(1.f+expf(-go));
    float cn = sf*c + si*tanhf(gg);
    float hn = so*tanhf(cn);
    g_c[b*Hh + h] = cn;
    hout[b*Hh + h] = hn;
}

// -------- logits GEMM + argmax partials + output writes --------
// grid 1000 blocks (32 v each), 128 threads; thread: 4 b x 4 v.
// Register-prefetch double buffering; reads g_hbuf[(t+1)&1].
__global__ void __launch_bounds__(128) k_logits(
    const float* __restrict__ W_out, const float* __restrict__ b_out,
    float* __restrict__ out, int t)
{
    __shared__ float sW[16*32];
    __shared__ float sH[16*68];
    __shared__ unsigned long long skey[64];
    int tx = threadIdx.x;
    int vblk = blockIdx.x * 32;
    int vg = tx >> 4, bg = tx & 15;
    if (tx < 64) skey[tx] = 0ull;
    const float* hin = g_hbuf[(t + 1) & 1];

    float acc[4][4];
    #pragma unroll
    for (int i = 0; i < 4; i++)
        #pragma unroll
        for (int j = 0; j < 4; j++) acc[i][j] = 0.f;

    int lv = tx >> 2, lkq = tx & 3;
    int lb0 = tx >> 2, lb1 = (tx + 128) >> 2;
    const float* wp  = W_out + (size_t)(vblk + lv)*Hh + lkq*4;
    const float* hp0 = hin + lb0*Hh + lkq*4;
    const float* hp1 = hin + lb1*Hh + lkq*4;
    float4 wreg  = *(const float4*)wp;
    float4 hreg0 = *(const float4*)hp0;
    float4 hreg1 = *(const float4*)hp1;

    for (int k0 = 0; k0 < Hh; k0 += 16){
        __syncthreads();
        sW[(lkq*4+0)*32+lv] = wreg.x; sW[(lkq*4+1)*32+lv] = wreg.y;
        sW[(lkq*4+2)*32+lv] = wreg.z; sW[(lkq*4+3)*32+lv] = wreg.w;
        sH[(lkq*4+0)*68+lb0] = hreg0.x; sH[(lkq*4+1)*68+lb0] = hreg0.y;
        sH[(lkq*4+2)*68+lb0] = hreg0.z; sH[(lkq*4+3)*68+lb0] = hreg0.w;
        sH[(lkq*4+0)*68+lb1] = hreg1.x; sH[(lkq*4+1)*68+lb1] = hreg1.y;
        sH[(lkq*4+2)*68+lb1] = hreg1.z; sH[(lkq*4+3)*68+lb1] = hreg1.w;
        __syncthreads();
        if (k0 + 16 < Hh){
            wreg  = *(const float4*)(wp  + k0 + 16);
            hreg0 = *(const float4*)(hp0 + k0 + 16);
            hreg1 = *(const float4*)(hp1 + k0 + 16);
        }
        #pragma unroll
        for (int k = 0; k < 16; k++){
            float4 h4 = *(const float4*)(sH + k*68 + bg*4);
            float4 w4 = *(const float4*)(sW + k*32 + vg*4);
            float hv[4] = {h4.x, h4.y, h4.z, h4.w};
            float wv[4] = {w4.x, w4.y, w4.z, w4.w};
            #pragma unroll
            for (int i = 0; i < 4; i++)
                #pragma unroll
                for (int j = 0; j < 4; j++)
                    acc[i][j] = fmaf(hv[i], wv[j], acc[i][j]);
        }
    }

    // epilogue: bias, vectorized logits + predicts-zero stores, argmax partials
    size_t base = (size_t)t * Bb * Vv;
    float* logits = out + 49152000ull;   // T*B*V
    int v0 = vblk + vg*4;
    float4 bo = *(const float4*)(b_out + v0);
    float4 zero4 = make_float4(0.f, 0.f, 0.f, 0.f);
    #pragma unroll
    for (int i = 0; i < 4; i++){
        int b = bg*4 + i;
        float4 val;
        val.x = acc[i][0] + bo.x; val.y = acc[i][1] + bo.y;
        val.z = acc[i][2] + bo.z; val.w = acc[i][3] + bo.w;
        size_t o = base + (size_t)b*Vv + v0;
        *(float4*)(logits + o) = val;
        *(float4*)(out + o) = zero4;     // predicts zero-fill
        unsigned long long k0_ = ((unsigned long long)fkey(val.x) << 32) | (unsigned long long)(0xFFFFFFFFu - (unsigned)(v0+0));
        unsigned long long k1_ = ((unsigned long long)fkey(val.y) << 32) | (unsigned long long)(0xFFFFFFFFu - (unsigned)(v0+1));
        unsigned long long k2_ = ((unsigned long long)fkey(val.z) << 32) | (unsigned long long)(0xFFFFFFFFu - (unsigned)(v0+2));
        unsigned long long k3_ = ((unsigned long long)fkey(val.w) << 32) | (unsigned long long)(0xFFFFFFFFu - (unsigned)(v0+3));
        unsigned long long best = k0_ > k1_ ? k0_ : k1_;
        if (k2_ > best) best = k2_;
        if (k3_ > best) best = k3_;
        atomicMax(&skey[b], best);
    }
    __syncthreads();
    if (tx < 64 && skey[tx]) atomicMax(&g_amax[(size_t)t*Bb + tx], skey[tx]);
}

// -------- trailing finalize for the last step (t = Tt-1) --------
__global__ void k_final(float* __restrict__ out){
    int b = threadIdx.x;
    if (b >= Bb) return;
    unsigned long long key = g_amax[(Tt-1)*Bb + b];
    int idx = dekey(key);
    out[(size_t)(Tt-1)*Bb*Vv + (size_t)b*Vv + idx] = 1.0f;
    out[98304000ull + (size_t)(Tt-1)*Bb + b] = g_mask[b];
}

extern "C" void kernel_launch(void* const* d_in, const int* in_sizes, int n_in,
                              void* d_out, int out_size){
    const float* eh    = (const float*)d_in[0];
    const float* ec    = (const float*)d_in[1];
    const float* W_ih  = (const float*)d_in[2];
    const float* W_hh  = (const float*)d_in[3];
    const float* b_ih  = (const float*)d_in[4];
    const float* b_hh  = (const float*)d_in[5];
    const float* W_out = (const float*)d_in[6];
    const float* b_out = (const float*)d_in[7];
    const float* x0    = (const float*)d_in[8];
    float* out = (float*)d_out;

    k_init<<<128, 256>>>(eh, ec);
    k_xv<<<Gg, 256>>>(W_ih, x0);
    for (int t = 0; t < Tt; t++){
        k_gates<<<128, 256>>>(W_hh, b_ih, b_hh, W_ih, out, t);
        k_logits<<<1000, 128>>>(W_out, b_out, out, t);
    }
    k_final<<<1, 64>>>(out);
}